// round 2
// baseline (speedup 1.0000x reference)
#include <cuda_runtime.h>
#include <math.h>

#define NBATCH 2
#define QLEN   2048
#define KLEN   2048
#define DMODEL 1024
#define NHEAD  16
#define DK     64

// ---------------- scratch (no allocations allowed) ----------------
__device__ float g_qp[(size_t)NBATCH * NHEAD * QLEN * DK];   // [n][h][q][d]
__device__ float g_kp[(size_t)NBATCH * NHEAD * KLEN * DK];   // [n][h][k][d]
__device__ float g_vp[(size_t)NBATCH * NHEAD * KLEN * DK];   // [n][h][k][d]
__device__ float g_ctx[(size_t)NBATCH * QLEN * DMODEL];      // [n][q][h*DK+d]

// ---------------- GEMM: C = A @ W^T + bias ----------------
// A: [M=4096][K=1024] row-major, W: [1024 out][1024 in] row-major.
// MODE 0: scatter output to head-major [n][h][row][d]
// MODE 1: plain row-major [m][o] (final output)
template<int MODE>
__global__ void __launch_bounds__(256, 2) gemm_xwT(
    const float* __restrict__ A, const float* __restrict__ W,
    const float* __restrict__ bias, float* __restrict__ C)
{
    const int K = DMODEL;
    __shared__ float As[16][132];   // [kk][m]
    __shared__ float Bs[16][132];   // [kk][n]

    const int bm = blockIdx.y * 128;
    const int bn = blockIdx.x * 128;
    const int tid = threadIdx.x;
    const int tx = tid & 15;
    const int ty = tid >> 4;

    float acc[8][8];
#pragma unroll
    for (int i = 0; i < 8; i++)
#pragma unroll
        for (int j = 0; j < 8; j++) acc[i][j] = 0.0f;

    const float* Aptr = A + (size_t)bm * K;
    const float* Wptr = W + (size_t)bn * K;

    for (int k0 = 0; k0 < K; k0 += 16) {
#pragma unroll
        for (int it = 0; it < 2; it++) {
            int lin = tid + it * 256;
            int row = lin >> 2;            // 0..127
            int kc  = (lin & 3) * 4;       // 0,4,8,12
            float4 a = *(const float4*)(Aptr + (size_t)row * K + k0 + kc);
            As[kc + 0][row] = a.x; As[kc + 1][row] = a.y;
            As[kc + 2][row] = a.z; As[kc + 3][row] = a.w;
            float4 b = *(const float4*)(Wptr + (size_t)row * K + k0 + kc);
            Bs[kc + 0][row] = b.x; Bs[kc + 1][row] = b.y;
            Bs[kc + 2][row] = b.z; Bs[kc + 3][row] = b.w;
        }
        __syncthreads();
#pragma unroll
        for (int kk = 0; kk < 16; kk++) {
            float a[8], b[8];
            *(float4*)(&a[0]) = *(const float4*)(&As[kk][ty * 8]);
            *(float4*)(&a[4]) = *(const float4*)(&As[kk][ty * 8 + 4]);
            *(float4*)(&b[0]) = *(const float4*)(&Bs[kk][tx * 8]);
            *(float4*)(&b[4]) = *(const float4*)(&Bs[kk][tx * 8 + 4]);
#pragma unroll
            for (int i = 0; i < 8; i++)
#pragma unroll
                for (int j = 0; j < 8; j++)
                    acc[i][j] += a[i] * b[j];
        }
        __syncthreads();
    }

#pragma unroll
    for (int i = 0; i < 8; i++) {
        int m = bm + ty * 8 + i;
#pragma unroll
        for (int j = 0; j < 8; j++) {
            int o = bn + tx * 8 + j;
            float v = acc[i][j] + bias[o];
            if (MODE == 0) {
                int n  = m >> 11;        // / QLEN
                int qr = m & (QLEN - 1);
                int hh = o >> 6;         // / DK
                int dd = o & (DK - 1);
                C[(((size_t)n * NHEAD + hh) * QLEN + qr) * DK + dd] = v;
            } else {
                C[(size_t)m * DMODEL + o] = v;
            }
        }
    }
}

// ---------------- flash-style attention (fp32) ----------------
// block = (n, h, 64-row q tile); 256 threads; 16x16 layout; 4x4 S and O tiles.
#define QSTRIDE 68
#define ATT_SMEM_BYTES ((2 * 64 * QSTRIDE + 2 * 64 * 64) * 4)

__global__ void __launch_bounds__(256) attention_kernel(const int* __restrict__ mask)
{
    extern __shared__ float smem[];
    float* QsT = smem;                       // [kk][r] 64 x QSTRIDE
    float* KsT = smem + 64 * QSTRIDE;        // [kk][c] 64 x QSTRIDE
    float* Vs  = smem + 2 * 64 * QSTRIDE;    // [k][c]  64 x 64
    float* Ps  = Vs + 64 * 64;               // [r][k]  64 x 64

    const int qt  = blockIdx.x;
    const int h   = blockIdx.y;
    const int n   = blockIdx.z;
    const int tid = threadIdx.x;
    const int tx  = tid & 15;
    const int ty  = tid >> 4;

    const float* qbase = g_qp + ((size_t)(n * NHEAD + h) * QLEN + (size_t)qt * 64) * DK;
    const float* kbase = g_kp + (size_t)(n * NHEAD + h) * KLEN * DK;
    const float* vbase = g_vp + (size_t)(n * NHEAD + h) * KLEN * DK;

    // load Q tile transposed: QsT[c][r] = Q[r][c]
#pragma unroll
    for (int it = 0; it < 4; it++) {
        int lin = tid + it * 256;
        int r = lin >> 4;
        int c = (lin & 15) * 4;
        float4 qv = *(const float4*)(qbase + r * DK + c);
        QsT[(c + 0) * QSTRIDE + r] = qv.x;
        QsT[(c + 1) * QSTRIDE + r] = qv.y;
        QsT[(c + 2) * QSTRIDE + r] = qv.z;
        QsT[(c + 3) * QSTRIDE + r] = qv.w;
    }

    float m_i[4], l_i[4], O[4][4];
#pragma unroll
    for (int i = 0; i < 4; i++) {
        m_i[i] = -1e30f;
        l_i[i] = 0.0f;
#pragma unroll
        for (int j = 0; j < 4; j++) O[i][j] = 0.0f;
    }

    const float scale = 0.125f;  // 1/sqrt(DK)

    for (int kt = 0; kt < KLEN / 64; kt++) {
        __syncthreads();   // prior PV reads of Vs/Ps done
        // load K tile transposed + V tile natural
#pragma unroll
        for (int it = 0; it < 4; it++) {
            int lin = tid + it * 256;
            int r = lin >> 4;
            int c = (lin & 15) * 4;
            float4 kv = *(const float4*)(kbase + (size_t)(kt * 64 + r) * DK + c);
            KsT[(c + 0) * QSTRIDE + r] = kv.x;
            KsT[(c + 1) * QSTRIDE + r] = kv.y;
            KsT[(c + 2) * QSTRIDE + r] = kv.z;
            KsT[(c + 3) * QSTRIDE + r] = kv.w;
            float4 vv = *(const float4*)(vbase + (size_t)(kt * 64 + r) * DK + c);
            *(float4*)(Vs + r * 64 + c) = vv;
        }
        __syncthreads();

        // S = Q K^T (4x4 per thread)
        float S[4][4];
#pragma unroll
        for (int i = 0; i < 4; i++)
#pragma unroll
            for (int j = 0; j < 4; j++) S[i][j] = 0.0f;

#pragma unroll 8
        for (int kk = 0; kk < 64; kk++) {
            float4 av = *(const float4*)(QsT + kk * QSTRIDE + ty * 4);
            float4 bv = *(const float4*)(KsT + kk * QSTRIDE + tx * 4);
            float a[4] = {av.x, av.y, av.z, av.w};
            float b[4] = {bv.x, bv.y, bv.z, bv.w};
#pragma unroll
            for (int i = 0; i < 4; i++)
#pragma unroll
                for (int j = 0; j < 4; j++)
                    S[i][j] += a[i] * b[j];
        }

        // scale + mask — mask is int32 (jax bool serialized as int32); nonzero -> -1e12
        size_t mbase = ((size_t)n * QLEN + (size_t)qt * 64 + ty * 4) * KLEN
                       + (size_t)kt * 64 + tx * 4;
#pragma unroll
        for (int i = 0; i < 4; i++) {
            int4 mm = *(const int4*)(mask + mbase + (size_t)i * KLEN);
            S[i][0] = mm.x ? -1e12f : S[i][0] * scale;
            S[i][1] = mm.y ? -1e12f : S[i][1] * scale;
            S[i][2] = mm.z ? -1e12f : S[i][2] * scale;
            S[i][3] = mm.w ? -1e12f : S[i][3] * scale;
        }

        // online softmax
#pragma unroll
        for (int i = 0; i < 4; i++) {
            float mx = fmaxf(fmaxf(S[i][0], S[i][1]), fmaxf(S[i][2], S[i][3]));
#pragma unroll
            for (int off = 8; off >= 1; off >>= 1)
                mx = fmaxf(mx, __shfl_xor_sync(0xffffffffu, mx, off, 16));
            float mnew = fmaxf(m_i[i], mx);
            float corr = __expf(m_i[i] - mnew);
            m_i[i] = mnew;
            float p0 = __expf(S[i][0] - mnew);
            float p1 = __expf(S[i][1] - mnew);
            float p2 = __expf(S[i][2] - mnew);
            float p3 = __expf(S[i][3] - mnew);
            *(float4*)(Ps + (ty * 4 + i) * 64 + tx * 4) = make_float4(p0, p1, p2, p3);
            float ls = p0 + p1 + p2 + p3;
#pragma unroll
            for (int off = 8; off >= 1; off >>= 1)
                ls += __shfl_xor_sync(0xffffffffu, ls, off, 16);
            l_i[i] = l_i[i] * corr + ls;
            O[i][0] *= corr; O[i][1] *= corr; O[i][2] *= corr; O[i][3] *= corr;
        }
        __syncthreads();   // Ps visible

        // O += P @ V
#pragma unroll 8
        for (int kk = 0; kk < 64; kk++) {
            float4 vv = *(const float4*)(Vs + kk * 64 + tx * 4);
            float p0 = Ps[(ty * 4 + 0) * 64 + kk];
            float p1 = Ps[(ty * 4 + 1) * 64 + kk];
            float p2 = Ps[(ty * 4 + 2) * 64 + kk];
            float p3 = Ps[(ty * 4 + 3) * 64 + kk];
            O[0][0] += p0 * vv.x; O[0][1] += p0 * vv.y; O[0][2] += p0 * vv.z; O[0][3] += p0 * vv.w;
            O[1][0] += p1 * vv.x; O[1][1] += p1 * vv.y; O[1][2] += p1 * vv.z; O[1][3] += p1 * vv.w;
            O[2][0] += p2 * vv.x; O[2][1] += p2 * vv.y; O[2][2] += p2 * vv.z; O[2][3] += p2 * vv.w;
            O[3][0] += p3 * vv.x; O[3][1] += p3 * vv.y; O[3][2] += p3 * vv.z; O[3][3] += p3 * vv.w;
        }
    }

    // epilogue: ctx[n][q][h*DK + d] = O / l
    float* obase = g_ctx + ((size_t)n * QLEN + (size_t)qt * 64) * DMODEL + h * DK;
#pragma unroll
    for (int i = 0; i < 4; i++) {
        float inv = 1.0f / l_i[i];
        float4 ov = make_float4(O[i][0] * inv, O[i][1] * inv, O[i][2] * inv, O[i][3] * inv);
        *(float4*)(obase + (size_t)(ty * 4 + i) * DMODEL + tx * 4) = ov;
    }
}

// ---------------- launch ----------------
extern "C" void kernel_launch(void* const* d_in, const int* in_sizes, int n_in,
                              void* d_out, int out_size)
{
    const float* q  = (const float*)d_in[0];
    const float* k  = (const float*)d_in[1];
    const float* v  = (const float*)d_in[2];
    const int*   mask = (const int*)d_in[3];
    const float* Wq = (const float*)d_in[4];
    const float* bq = (const float*)d_in[5];
    const float* Wk = (const float*)d_in[6];
    const float* bk = (const float*)d_in[7];
    const float* Wv = (const float*)d_in[8];
    const float* bv = (const float*)d_in[9];
    const float* Wo = (const float*)d_in[10];
    const float* bo = (const float*)d_in[11];
    float* out = (float*)d_out;

    float *qp, *kp, *vp, *ctx;
    cudaGetSymbolAddress((void**)&qp,  g_qp);
    cudaGetSymbolAddress((void**)&kp,  g_kp);
    cudaGetSymbolAddress((void**)&vp,  g_vp);
    cudaGetSymbolAddress((void**)&ctx, g_ctx);

    cudaFuncSetAttribute(attention_kernel,
                         cudaFuncAttributeMaxDynamicSharedMemorySize, ATT_SMEM_BYTES);

    dim3 gridp(DMODEL / 128, (NBATCH * QLEN) / 128);
    gemm_xwT<0><<<gridp, 256>>>(q, Wq, bq, qp);
    gemm_xwT<0><<<gridp, 256>>>(k, Wk, bk, kp);
    gemm_xwT<0><<<gridp, 256>>>(v, Wv, bv, vp);

    attention_kernel<<<dim3(QLEN / 64, NHEAD, NBATCH), 256, ATT_SMEM_BYTES>>>(mask);

    gemm_xwT<1><<<gridp, 256>>>(ctx, Wo, bo, out);
}